// round 2
// baseline (speedup 1.0000x reference)
#include <cuda_runtime.h>

// BatchDotPred: out[e] = dot(feat[src[e]], feat[dst[e]]), D=128.
// One warp per edge; each lane handles one float4 (4 floats) of each row.
// feat (51.2 MB) fits in L2 -> expect L2-bandwidth-bound.

__global__ void __launch_bounds__(256) batch_dot_kernel(
    const int2* __restrict__ edges,     // n_edges pairs (src, dst)
    const float4* __restrict__ feat,    // n_nodes x 32 float4 (=128 floats)
    float* __restrict__ out,            // n_edges
    int n_edges)
{
    int gtid = blockIdx.x * blockDim.x + threadIdx.x;
    int e    = gtid >> 5;        // warp index = edge index
    int lane = gtid & 31;
    if (e >= n_edges) return;

    int2 ed = edges[e];          // broadcast load (all lanes same address)

    const float4* __restrict__ srow = feat + (size_t)ed.x * 32;
    const float4* __restrict__ drow = feat + (size_t)ed.y * 32;

    float4 a = srow[lane];       // coalesced 512B per warp
    float4 b = drow[lane];

    float s = a.x * b.x + a.y * b.y + a.z * b.z + a.w * b.w;

    // warp reduction
    #pragma unroll
    for (int off = 16; off > 0; off >>= 1)
        s += __shfl_xor_sync(0xffffffffu, s, off);

    if (lane == 0) out[e] = s;
}

extern "C" void kernel_launch(void* const* d_in, const int* in_sizes, int n_in,
                              void* d_out, int out_size)
{
    const int2*   edges = (const int2*)d_in[0];    // int32 (E,2)
    const float4* feat  = (const float4*)d_in[1];  // float32 (N,128)
    float*        out   = (float*)d_out;

    int n_edges = in_sizes[0] / 2;

    const int THREADS = 256;               // 8 edges per block
    int edges_per_block = THREADS / 32;
    int blocks = (n_edges + edges_per_block - 1) / edges_per_block;

    batch_dot_kernel<<<blocks, THREADS>>>(edges, feat, out, n_edges);
}